// round 4
// baseline (speedup 1.0000x reference)
#include <cuda_runtime.h>
#include <cuda_fp16.h>
#include <math.h>

// ---------------------------------------------------------------------------
// GaussCrossEntropyLoss — single-pass persistent kernel.
// Phase A: read pred/coord/segment ONCE, compute c = CE*focal, cache (z, c)
//          in shared memory, reduce per-cloud z statistics.
// Software grid barrier (all blocks co-resident by construction).
// Phase B: mu from stats, acc += c * gauss_w(z, mu), last block writes mean.
// ---------------------------------------------------------------------------

#define FULLMASK 0xFFFFFFFFu
#define MAXB    8
#define THREADS 256
#define ITERS   7
#define GROUPS  (ITERS * THREADS)        // float4-groups per block = 1792
#define CHUNK   (GROUPS * 4)             // points per block = 7168
#define MAXBLK  592                      // 148 SMs * 4 blocks

__device__ float g_gmax[MAXB];
__device__ float g_pmin[MAXB];
__device__ float g_zmin[MAXB];
__device__ float g_zmax[MAXB];
__device__ float g_acc;
__device__ int   g_bar;
__device__ int   g_done;

__device__ __forceinline__ void atomicMaxF(float* a, float v) {
    if (v >= 0.0f) atomicMax((int*)a, __float_as_int(v));
    else           atomicMin((unsigned int*)a, __float_as_uint(v));
}
__device__ __forceinline__ void atomicMinF(float* a, float v) {
    if (v >= 0.0f) atomicMin((int*)a, __float_as_int(v));
    else           atomicMax((unsigned int*)a, __float_as_uint(v));
}

__device__ __forceinline__ int batch_of(int i, const int* s_off) {
    int b = 0;
#pragma unroll
    for (int k = 0; k < MAXB; k++) b += (i >= s_off[k]);
    return b;
}

__global__ void k_init() {
    int t = threadIdx.x;
    if (t == 0) { g_acc = 0.0f; g_bar = 0; g_done = 0; }
    if (t < MAXB) {
        g_gmax[t] = -INFINITY;
        g_pmin[t] =  INFINITY;
        g_zmin[t] =  INFINITY;
        g_zmax[t] = -INFINITY;
    }
}

// c = cross-entropy * focal (mu-independent part of the loss)
__device__ __forceinline__ float ce_focal(float x0, float x1, int s) {
    float m   = fmaxf(x0, x1);
    float mn  = fminf(x0, x1);
    float e   = __expf(mn - m);
    float lse = m + __logf(1.0f + e);
    float lt  = (s ? x1 : x0) - lse;       // log p_t
    float pt  = __expf(lt);
    float om  = 1.0f - pt;
    return (-lt) * om * om;                // alpha=1, gamma=2
}

// asymmetric gaussian weight
__device__ __forceinline__ float gauss_w(float zz, float mu) {
    float d = zz - mu;
    float dd = d * d;
    if (zz <= mu) return __expf(-50.0f * dd);                      // 1/(2*0.1^2)
    return (d > 0.8f) ? 0.1f : __expf(-3.125f * dd);               // 1/(2*0.4^2)
}

__global__ void __launch_bounds__(THREADS, 4)
k_fused(const float* __restrict__ pred, const float* __restrict__ coord,
        const int* __restrict__ segment, const int* __restrict__ offset,
        float* __restrict__ out, int n, int nb, int nblocks, float inv_n)
{
    __shared__ float  s_z[GROUPS * 4];     // 28672 B
    __shared__ __half s_c[GROUPS * 4];     // 14336 B
    __shared__ int    s_off[MAXB];
    __shared__ float  s_gmax[MAXB], s_pmin[MAXB], s_zmin[MAXB], s_zmax[MAXB];
    __shared__ float  s_mu[MAXB];
    __shared__ float  s_red[THREADS / 32];

    const int tid = threadIdx.x;
    if (tid < MAXB) {
        s_off[tid]  = (tid < nb) ? offset[tid] : 0x7FFFFFFF;
        s_gmax[tid] = -INFINITY;  s_pmin[tid] = INFINITY;
        s_zmin[tid] =  INFINITY;  s_zmax[tid] = -INFINITY;
    }
    __syncthreads();

    const int cbase = blockIdx.x * CHUNK;
    int  bfirst = 0;
    bool uni    = false;
    if (cbase < n) {
        bfirst = batch_of(cbase, s_off);
        int last = min(cbase + CHUNK, n) - 1;
        uni = (cbase + CHUNK <= n) && (bfirst == batch_of(last, s_off));
    }

    // ---------------- Phase A ----------------
    float lg = -INFINITY, lp = INFINITY, lmn = INFINITY, lmx = -INFINITY;

#pragma unroll
    for (int it = 0; it < ITERS; it++) {
        const int g4    = cbase / 4 + it * THREADS + tid;  // float4-group idx
        const int pbase = g4 * 4;
        const int ci    = it * THREADS + tid;              // cache group idx

        if (pbase + 3 < n) {
            const float4* p4 = (const float4*)pred;
            float4 pa = p4[2 * g4 + 0];
            float4 pb = p4[2 * g4 + 1];
            const float4* c4 = (const float4*)coord;
            float4 ca = c4[3 * g4 + 0];
            float4 cb = c4[3 * g4 + 1];
            float4 cc = c4[3 * g4 + 2];
            int4   s4 = ((const int4*)segment)[g4];

            float z[4]  = { ca.z, cb.y, cc.x, cc.w };
            float x0[4] = { pa.x, pa.z, pb.x, pb.z };
            float x1[4] = { pa.y, pa.w, pb.y, pb.w };
            int   sg[4] = { s4.x, s4.y, s4.z, s4.w };

#pragma unroll
            for (int j = 0; j < 4; j++) {
                float c = ce_focal(x0[j], x1[j], sg[j]);
                s_z[j * GROUPS + ci] = z[j];
                s_c[j * GROUPS + ci] = __float2half(c);
            }
            if (uni) {
#pragma unroll
                for (int j = 0; j < 4; j++) {
                    float zz = z[j];
                    if (sg[j] == 0) lg = fmaxf(lg, zz);
                    else            lp = fminf(lp, zz);
                    lmn = fminf(lmn, zz);
                    lmx = fmaxf(lmx, zz);
                }
            } else {   // cloud-boundary block (rare)
#pragma unroll
                for (int j = 0; j < 4; j++) {
                    int b = batch_of(pbase + j, s_off);
                    float zz = z[j];
                    if (sg[j] == 0) atomicMaxF(&s_gmax[b], zz);
                    else            atomicMinF(&s_pmin[b], zz);
                    atomicMinF(&s_zmin[b], zz);
                    atomicMaxF(&s_zmax[b], zz);
                }
            }
        } else {       // tail (last block only)
#pragma unroll
            for (int j = 0; j < 4; j++) {
                int i = pbase + j;
                if (i < n) {
                    float zz = coord[3 * i + 2];
                    int   ss = segment[i];
                    float c  = ce_focal(pred[2 * i], pred[2 * i + 1], ss);
                    s_z[j * GROUPS + ci] = zz;
                    s_c[j * GROUPS + ci] = __float2half(c);
                    int b = batch_of(i, s_off);
                    if (ss == 0) atomicMaxF(&s_gmax[b], zz);
                    else         atomicMinF(&s_pmin[b], zz);
                    atomicMinF(&s_zmin[b], zz);
                    atomicMaxF(&s_zmax[b], zz);
                }
            }
        }
    }

    if (uni) {   // warp reduce, then one smem update per warp
#pragma unroll
        for (int o = 16; o > 0; o >>= 1) {
            lg  = fmaxf(lg,  __shfl_xor_sync(FULLMASK, lg,  o));
            lp  = fminf(lp,  __shfl_xor_sync(FULLMASK, lp,  o));
            lmn = fminf(lmn, __shfl_xor_sync(FULLMASK, lmn, o));
            lmx = fmaxf(lmx, __shfl_xor_sync(FULLMASK, lmx, o));
        }
        if ((tid & 31) == 0) {
            if (lg > -INFINITY) atomicMaxF(&s_gmax[bfirst], lg);
            if (lp <  INFINITY) atomicMinF(&s_pmin[bfirst], lp);
            atomicMinF(&s_zmin[bfirst], lmn);
            atomicMaxF(&s_zmax[bfirst], lmx);
        }
    }
    __syncthreads();

    // block -> global stats (identity-filtered), then release fence
    if (tid < 32) {
        int b = tid >> 2, k = tid & 3;
        if      (k == 0) { float v = s_gmax[b]; if (v > -INFINITY) atomicMaxF(&g_gmax[b], v); }
        else if (k == 1) { float v = s_pmin[b]; if (v <  INFINITY) atomicMinF(&g_pmin[b], v); }
        else if (k == 2) { float v = s_zmin[b]; if (v <  INFINITY) atomicMinF(&g_zmin[b], v); }
        else             { float v = s_zmax[b]; if (v > -INFINITY) atomicMaxF(&g_zmax[b], v); }
        __threadfence();
    }
    __syncthreads();

    // ---------------- grid barrier (all blocks resident) ----------------
    if (tid == 0) {
        atomicAdd(&g_bar, 1);
        while (*((volatile int*)&g_bar) < nblocks) __nanosleep(64);
        __threadfence();
    }
    __syncthreads();

    if (tid < MAXB) {
        float g = *((volatile float*)&g_gmax[tid]); if (isinf(g)) g = *((volatile float*)&g_zmin[tid]);
        float p = *((volatile float*)&g_pmin[tid]); if (isinf(p)) p = *((volatile float*)&g_zmax[tid]);
        s_mu[tid] = g + (p - g) * 0.5f;    // exact reference expression
    }
    __syncthreads();

    // ---------------- Phase B ----------------
    float acc = 0.0f;
    const float mu_u = s_mu[uni ? bfirst : 0];

#pragma unroll
    for (int it = 0; it < ITERS; it++) {
        const int g4    = cbase / 4 + it * THREADS + tid;
        const int pbase = g4 * 4;
        const int ci    = it * THREADS + tid;
        if (uni) {
#pragma unroll
            for (int j = 0; j < 4; j++) {
                float z = s_z[j * GROUPS + ci];
                float c = __half2float(s_c[j * GROUPS + ci]);
                acc += c * gauss_w(z, mu_u);
            }
        } else {
#pragma unroll
            for (int j = 0; j < 4; j++) {
                int i = pbase + j;
                if (i < n) {
                    float z = s_z[j * GROUPS + ci];
                    float c = __half2float(s_c[j * GROUPS + ci]);
                    int   b = batch_of(i, s_off);
                    acc += c * gauss_w(z, s_mu[b]);
                }
            }
        }
    }

#pragma unroll
    for (int o = 16; o > 0; o >>= 1)
        acc += __shfl_xor_sync(FULLMASK, acc, o);
    if ((tid & 31) == 0) s_red[tid >> 5] = acc;
    __syncthreads();

    if (tid == 0) {
        float s = 0.0f;
#pragma unroll
        for (int k = 0; k < THREADS / 32; k++) s += s_red[k];
        atomicAdd(&g_acc, s);
        __threadfence();
        int old = atomicAdd(&g_done, 1);
        if (old == nblocks - 1)
            out[0] = *((volatile float*)&g_acc) * inv_n;   // last block writes mean
    }
}

// ---------------------------------------------------------------------------
extern "C" void kernel_launch(void* const* d_in, const int* in_sizes, int n_in,
                              void* d_out, int out_size)
{
    const float* pred    = (const float*)d_in[0];
    const float* coord   = (const float*)d_in[1];
    const int*   segment = (const int*)d_in[2];
    const int*   offset  = (const int*)d_in[3];
    int n  = in_sizes[2];
    int nb = in_sizes[3]; if (nb > MAXB) nb = MAXB;

    int nblocks = (n + CHUNK - 1) / CHUNK;          // 586 for N=4.19M (<=592 resident)
    if (nblocks > MAXBLK) nblocks = MAXBLK;         // shape contract: N <= 592*7168

    k_init<<<1, 32>>>();
    k_fused<<<nblocks, THREADS>>>(pred, coord, segment, offset,
                                  (float*)d_out, n, nb, nblocks, 1.0f / (float)n);
}

// round 5
// speedup vs baseline: 1.0760x; 1.0760x over previous
#include <cuda_runtime.h>
#include <math.h>

// ---------------------------------------------------------------------------
// GaussCrossEntropyLoss — two-pass, L2-reuse design.
// Pass 1 (k_stats): stream coord+segment (64 MB, DRAM) -> per-cloud z stats.
//                   coord+segment stay resident in L2 (126 MB).
// Pass 2 (k_loss):  stream pred (32 MB, DRAM) + coord.z+segment (L2 hits),
//                   loss = CE*focal*gauss_w, 32-slot atomic sum; the LAST
//                   finishing block reduces the slots and writes the mean.
// ---------------------------------------------------------------------------

#define FULLMASK 0xFFFFFFFFu
#define MAXB 8

__device__ float g_gmax[MAXB];   // max z over ground points  (-inf if none)
__device__ float g_pmin[MAXB];   // min z over plant points   (+inf if none)
__device__ float g_zmin[MAXB];   // min z overall
__device__ float g_zmax[MAXB];   // max z overall
__device__ float g_acc[32];      // spread partial loss sums
__device__ int   g_done;         // pass-2 completion counter

__device__ __forceinline__ void atomicMaxF(float* a, float v) {
    if (v >= 0.0f) atomicMax((int*)a, __float_as_int(v));
    else           atomicMin((unsigned int*)a, __float_as_uint(v));
}
__device__ __forceinline__ void atomicMinF(float* a, float v) {
    if (v >= 0.0f) atomicMin((int*)a, __float_as_int(v));
    else           atomicMax((unsigned int*)a, __float_as_uint(v));
}

// searchsorted(offset, i, side='right') == count of offsets <= i
__device__ __forceinline__ int batch_of(int i, const int* s_off) {
    int b = 0;
#pragma unroll
    for (int k = 0; k < MAXB; k++) b += (i >= s_off[k]);
    return b;
}

__global__ void k_init() {
    int t = threadIdx.x;
    g_acc[t] = 0.0f;
    if (t == 0) g_done = 0;
    if (t < MAXB) {
        g_gmax[t] = -INFINITY;
        g_pmin[t] =  INFINITY;
        g_zmin[t] =  INFINITY;
        g_zmax[t] = -INFINITY;
    }
}

// ---------------------------------------------------------------------------
// Pass 1: per-cloud z statistics (also warms L2 with coord+segment)
// ---------------------------------------------------------------------------
__global__ void __launch_bounds__(256)
k_stats(const float* __restrict__ coord, const int* __restrict__ segment,
        const int* __restrict__ offset, int n, int nb)
{
    __shared__ int   s_off[MAXB];
    __shared__ float s_gmax[MAXB], s_pmin[MAXB], s_zmin[MAXB], s_zmax[MAXB];
    const int tid = threadIdx.x;
    if (tid < MAXB) {
        s_off[tid]  = (tid < nb) ? offset[tid] : 0x7FFFFFFF;
        s_gmax[tid] = -INFINITY;  s_pmin[tid] = INFINITY;
        s_zmin[tid] =  INFINITY;  s_zmax[tid] = -INFINITY;
    }
    __syncthreads();

    const int t    = blockIdx.x * blockDim.x + tid;
    const int base = t * 4;
    const bool fullv = (base + 3 < n);

    float z[4];
    int   sg[4];
    int   b0 = 0;
    bool  uni = false;

    if (fullv) {
        const float4* c4 = (const float4*)coord;
        float4 ca = c4[3 * t + 0];
        float4 cb = c4[3 * t + 1];
        float4 cc = c4[3 * t + 2];
        z[0] = ca.z; z[1] = cb.y; z[2] = cc.x; z[3] = cc.w;
        int4 s4 = ((const int4*)segment)[t];
        sg[0] = s4.x; sg[1] = s4.y; sg[2] = s4.z; sg[3] = s4.w;
        b0 = batch_of(base, s_off);
        uni = (b0 == batch_of(base + 3, s_off));   // batch ids monotonic
    }

    const int  wb   = __shfl_sync(FULLMASK, b0, 0);
    const bool wuni = __all_sync(FULLMASK, fullv && uni && (b0 == wb));

    if (wuni) {
        // fast path: whole warp is one cloud — register + shuffle reduction
        float lg = -INFINITY, lp = INFINITY, lmn = INFINITY, lmx = -INFINITY;
#pragma unroll
        for (int j = 0; j < 4; j++) {
            float zz = z[j];
            if (sg[j] == 0) lg = fmaxf(lg, zz); else lp = fminf(lp, zz);
            lmn = fminf(lmn, zz);
            lmx = fmaxf(lmx, zz);
        }
#pragma unroll
        for (int o = 16; o > 0; o >>= 1) {
            lg  = fmaxf(lg,  __shfl_xor_sync(FULLMASK, lg,  o));
            lp  = fminf(lp,  __shfl_xor_sync(FULLMASK, lp,  o));
            lmn = fminf(lmn, __shfl_xor_sync(FULLMASK, lmn, o));
            lmx = fmaxf(lmx, __shfl_xor_sync(FULLMASK, lmx, o));
        }
        if ((tid & 31) == 0) {
            if (lg > -INFINITY) atomicMaxF(&s_gmax[wb], lg);
            if (lp <  INFINITY) atomicMinF(&s_pmin[wb], lp);
            atomicMinF(&s_zmin[wb], lmn);
            atomicMaxF(&s_zmax[wb], lmx);
        }
    } else {
        // slow path: boundary / tail lanes — per-point smem atomics
#pragma unroll
        for (int j = 0; j < 4; j++) {
            int i = base + j;
            if (i < n) {
                float zz = fullv ? z[j]  : coord[3 * i + 2];
                int   ss = fullv ? sg[j] : segment[i];
                int   b  = batch_of(i, s_off);
                if (ss == 0) atomicMaxF(&s_gmax[b], zz);
                else         atomicMinF(&s_pmin[b], zz);
                atomicMinF(&s_zmin[b], zz);
                atomicMaxF(&s_zmax[b], zz);
            }
        }
    }
    __syncthreads();

    // block -> global: only non-identity values escape (<=4 REDs typical)
    if (tid < 32) {
        int b = tid >> 2, k = tid & 3;
        if      (k == 0) { float v = s_gmax[b]; if (v > -INFINITY) atomicMaxF(&g_gmax[b], v); }
        else if (k == 1) { float v = s_pmin[b]; if (v <  INFINITY) atomicMinF(&g_pmin[b], v); }
        else if (k == 2) { float v = s_zmin[b]; if (v <  INFINITY) atomicMinF(&g_zmin[b], v); }
        else             { float v = s_zmax[b]; if (v > -INFINITY) atomicMaxF(&g_zmax[b], v); }
    }
}

// ---------------------------------------------------------------------------
// Pass 2: focal CE * gaussian weight, summed; last block writes the mean.
// coord + segment reads should hit L2 (warmed by pass 1).
// ---------------------------------------------------------------------------
__device__ __forceinline__ float point_loss(float x0, float x1, int s,
                                            float zz, float mu)
{
    // log_softmax over 2 classes
    float m   = fmaxf(x0, x1);
    float mn  = fminf(x0, x1);
    float lse = m + __logf(1.0f + __expf(mn - m));
    float lt  = (s ? x1 : x0) - lse;      // log p_t
    float pt  = __expf(lt);
    float om  = 1.0f - pt;
    float fw  = om * om;                  // focal (alpha=1, gamma=2)
    // asymmetric gaussian weight
    float d = zz - mu;
    float dd = d * d;
    float w;
    if (zz <= mu) w = __expf(-50.0f * dd);                      // 1/(2*0.1^2)
    else          w = (d > 0.8f) ? 0.1f : __expf(-3.125f * dd); // 1/(2*0.4^2)
    return (-lt) * fw * w;
}

__global__ void __launch_bounds__(256)
k_loss(const float* __restrict__ pred, const float* __restrict__ coord,
       const int* __restrict__ segment, const int* __restrict__ offset,
       float* __restrict__ out, int n, int nb, int nblocks, float inv_n)
{
    __shared__ int   s_off[MAXB];
    __shared__ float s_mu[MAXB];
    __shared__ float s_part[8];
    const int tid = threadIdx.x;
    if (tid < MAXB) {
        s_off[tid] = (tid < nb) ? offset[tid] : 0x7FFFFFFF;
        float g = g_gmax[tid]; if (isinf(g)) g = g_zmin[tid];
        float p = g_pmin[tid]; if (isinf(p)) p = g_zmax[tid];
        s_mu[tid] = g + (p - g) * 0.5f;   // exact reference expression
    }
    __syncthreads();

    const int t    = blockIdx.x * blockDim.x + tid;
    const int base = t * 4;
    float acc = 0.0f;

    if (base + 3 < n) {
        const float4* p4 = (const float4*)pred;
        float4 pa = p4[2 * t + 0];
        float4 pb = p4[2 * t + 1];
        const float4* c4 = (const float4*)coord;
        float4 ca = c4[3 * t + 0];
        float4 cb = c4[3 * t + 1];
        float4 cc = c4[3 * t + 2];
        int4 s4 = ((const int4*)segment)[t];

        float z[4]  = { ca.z, cb.y, cc.x, cc.w };
        float x0[4] = { pa.x, pa.z, pb.x, pb.z };
        float x1[4] = { pa.y, pa.w, pb.y, pb.w };
        int   sg[4] = { s4.x, s4.y, s4.z, s4.w };
#pragma unroll
        for (int j = 0; j < 4; j++) {
            int b = batch_of(base + j, s_off);
            acc += point_loss(x0[j], x1[j], sg[j], z[j], s_mu[b]);
        }
    } else {
#pragma unroll
        for (int j = 0; j < 4; j++) {
            int i = base + j;
            if (i < n) {
                int b = batch_of(i, s_off);
                acc += point_loss(pred[2 * i], pred[2 * i + 1], segment[i],
                                  coord[3 * i + 2], s_mu[b]);
            }
        }
    }

#pragma unroll
    for (int o = 16; o > 0; o >>= 1)
        acc += __shfl_xor_sync(FULLMASK, acc, o);
    if ((tid & 31) == 0) s_part[tid >> 5] = acc;
    __syncthreads();

    if (tid == 0) {
        float s = 0.0f;
#pragma unroll
        for (int k = 0; k < 8; k++) s += s_part[k];
        atomicAdd(&g_acc[blockIdx.x & 31], s);
        __threadfence();
        int old = atomicAdd(&g_done, 1);
        if (old == nblocks - 1) {
            // last finishing block: all other blocks' g_acc adds are fenced
            // before their g_done increments, hence visible here.
            float tot = 0.0f;
#pragma unroll
            for (int k = 0; k < 32; k++)
                tot += *((volatile float*)&g_acc[k]);
            out[0] = tot * inv_n;
        }
    }
}

// ---------------------------------------------------------------------------
extern "C" void kernel_launch(void* const* d_in, const int* in_sizes, int n_in,
                              void* d_out, int out_size)
{
    const float* pred    = (const float*)d_in[0];
    const float* coord   = (const float*)d_in[1];
    const int*   segment = (const int*)d_in[2];
    const int*   offset  = (const int*)d_in[3];
    int n  = in_sizes[2];
    int nb = in_sizes[3]; if (nb > MAXB) nb = MAXB;

    const int threads = 256;
    const int ppb     = threads * 4;
    const int blocks  = (n + ppb - 1) / ppb;

    k_init<<<1, 32>>>();
    k_stats<<<blocks, threads>>>(coord, segment, offset, n, nb);
    k_loss<<<blocks, threads>>>(pred, coord, segment, offset,
                                (float*)d_out, n, nb, blocks, 1.0f / (float)n);
}